// round 14
// baseline (speedup 1.0000x reference)
#include <cuda_runtime.h>
#include <math.h>
#include <stdint.h>

#define Bc 4
#define Sq 2048
#define Dm 1024
#define Hh 16
#define HDIM 64
#define Ff 4096
#define Ee 8
#define Kk 2
#define Tt (Bc*Sq)   /* 8192 tokens */

// ------------------------- scratch (device globals; no allocs allowed) ----
__device__ float g_q  [(size_t)Tt*Dm];
__device__ float g_k  [(size_t)Tt*Dm];
__device__ float g_v  [(size_t)Tt*Dm];
__device__ float g_att[(size_t)Tt*Dm];   // bf16 hi/lo planes (cast)
__device__ float g_prj[(size_t)Tt*Dm];
__device__ float g_x1 [(size_t)Tt*Dm];
__device__ float g_moe[(size_t)Tt*Dm];
__device__ float g_h  [(size_t)Tt*Kk*Ff];  // packed hidden as hi/lo planes
__device__ int   g_tok[Ee*Tt];
__device__ float g_wt [Ee*Tt];
__device__ int   g_cnt[Ee];
__device__ int   g_off[Ee];
__device__ float g_gsum[Ee];
// pre-split bf16x2 hi/lo planes.
// A-side (activations): k-major [rows][K/2], lo plane follows hi plane.
__device__ uint32_t g_xc [(size_t)Tt*Dm];
__device__ uint32_t g_x1c[(size_t)Tt*Dm];
// B-side (weights): n-major [N][K/2] per matrix/expert, lo planes follow all hi.
__device__ uint32_t g_wqc[(size_t)Dm*Dm];
__device__ uint32_t g_wkc[(size_t)Dm*Dm];
__device__ uint32_t g_wvc[(size_t)Dm*Dm];
__device__ uint32_t g_woc[(size_t)Dm*Dm];
__device__ uint32_t g_w1c[(size_t)Ee*Dm*Ff];
__device__ uint32_t g_w2c[(size_t)Ee*Ff*Dm];

// ------------------------- helpers -----------------------------------------
__device__ __forceinline__ void split2(float x0, float x1,
                                       uint32_t& hi, uint32_t& lo)
{
    uint32_t h;
    asm("cvt.rn.bf16x2.f32 %0, %1, %2;" : "=r"(h) : "f"(x1), "f"(x0));
    float h0 = __uint_as_float(h << 16);
    float h1 = __uint_as_float(h & 0xffff0000u);
    uint32_t l;
    asm("cvt.rn.bf16x2.f32 %0, %1, %2;" : "=r"(l) : "f"(x1 - h1), "f"(x0 - h0));
    hi = h; lo = l;
}

__device__ __forceinline__ void mma_bf16(float c[4],
    uint32_t a0, uint32_t a1, uint32_t a2, uint32_t a3,
    uint32_t b0, uint32_t b1)
{
    asm volatile(
        "mma.sync.aligned.m16n8k16.row.col.f32.bf16.bf16.f32 "
        "{%0,%1,%2,%3}, {%4,%5,%6,%7}, {%8,%9}, {%0,%1,%2,%3};"
        : "+f"(c[0]), "+f"(c[1]), "+f"(c[2]), "+f"(c[3])
        : "r"(a0), "r"(a1), "r"(a2), "r"(a3), "r"(b0), "r"(b1));
}

__device__ __forceinline__ void ldsm_x4(uint32_t& r0, uint32_t& r1,
                                        uint32_t& r2, uint32_t& r3,
                                        uint32_t addr)
{
    asm volatile("ldmatrix.sync.aligned.m8n8.x4.shared.b16 {%0,%1,%2,%3}, [%4];"
                 : "=r"(r0), "=r"(r1), "=r"(r2), "=r"(r3) : "r"(addr));
}
__device__ __forceinline__ void ldsm_x2(uint32_t& r0, uint32_t& r1, uint32_t addr)
{
    asm volatile("ldmatrix.sync.aligned.m8n8.x2.shared.b16 {%0,%1}, [%2];"
                 : "=r"(r0), "=r"(r1) : "r"(addr));
}

#define CP_ASYNC16(dst, src) \
    asm volatile("cp.async.cg.shared.global [%0], [%1], 16;" :: "r"(dst), "l"(src))
#define CP_COMMIT() asm volatile("cp.async.commit_group;")

// ------------------------- conversion kernels ------------------------------
// A-side: pack pairs of consecutive floats -> hi/lo planes (k-major rows)
__global__ void conv_rows(const float* __restrict__ src,
                          uint32_t* __restrict__ dst, int n)
{
    int half = n >> 1;
    for (int i = blockIdx.x * blockDim.x + threadIdx.x; i < half;
         i += gridDim.x * blockDim.x) {
        float2 v = ((const float2*)src)[i];
        uint32_t h, l;
        split2(v.x, v.y, h, l);
        dst[i] = h; dst[half + i] = l;
    }
}

// B-side: W[Kdim][N] row-major -> n-major planes dst[N][Kdim/2] (+ lo at loOff)
// Tiled transpose: block (32,8) handles a 32 kpair x 32 n tile; blockIdx.z = expert.
__global__ void convT(const float* __restrict__ src, uint32_t* __restrict__ dst,
                      int Kdim, int N, size_t loOff)
{
    __shared__ uint32_t sh[32][33], sl[32][33];
    const int z = blockIdx.z;
    src += (size_t)z * Kdim * N;
    const int KW = Kdim >> 1;
    dst += (size_t)z * N * KW;

    const int kp0 = blockIdx.y * 32, n0 = blockIdx.x * 32;
    const int tx = threadIdx.x, ty = threadIdx.y;

    #pragma unroll
    for (int s = 0; s < 32; s += 8) {
        int kp = kp0 + ty + s;
        float a = src[(size_t)(2 * kp) * N + n0 + tx];
        float b = src[(size_t)(2 * kp + 1) * N + n0 + tx];
        uint32_t h, l;
        split2(a, b, h, l);
        sh[ty + s][tx] = h; sl[ty + s][tx] = l;
    }
    __syncthreads();
    #pragma unroll
    for (int s = 0; s < 32; s += 8) {
        int n = n0 + ty + s;
        dst[(size_t)n * KW + kp0 + tx] = sh[tx][ty + s];
        dst[loOff + (size_t)n * KW + kp0 + tx] = sl[tx][ty + s];
    }
}

// ------------------------- ldmatrix bf16x3 GEMM ----------------------------
// A: k-major hi/lo planes [rows][K/2]; B: n-major hi/lo planes [N][K/2].
// 128x128 tile, BK=32, 256 threads (2x4 warps, 64x32 each), double-buffered
// cp.async; fragments via ldmatrix (conflict-free at pitch 20).
// smem stage (bytes): Ah@0 Al@10240 Bh@20480 Bl@30720; stage=40960, 2 stages.
#define GSMEM_BYTES 81920

template<int MODE>
__global__ __launch_bounds__(256, 2)
void gemm_tc(const uint32_t* __restrict__ Ahp, size_t aLoOff,
             const uint32_t* __restrict__ Bhp, size_t bLoOff,
             const float* __restrict__ bias,
             float* __restrict__ C,
             int M, int N, int Kd,
             const int* __restrict__ cnt,
             const int* __restrict__ off,
             const int* __restrict__ tokl,
             const float* __restrict__ wtl)
{
    extern __shared__ uint32_t dsm[];

    const int e  = blockIdx.z;
    const int m0 = blockIdx.y * 128;
    const int n0 = blockIdx.x * 128;

    int Me = M, hbase = 0;
    const uint32_t* Bh_e = Bhp;
    const float* bp = bias;
    const int KW = Kd >> 1;
    if (MODE != 0) {
        Me = cnt[e];
        if (m0 >= Me) return;
        Bh_e = Bhp + (size_t)e * N * KW;
        bp = bias + (size_t)e * N;
        hbase = off[e];
    }

    const int tid  = threadIdx.x;
    const int lane = tid & 31, warp = tid >> 5;
    const int wm = warp >> 2, wn = warp & 3;
    const int tr = lane >> 2, tc = lane & 3;

    // ---- loaders: thread -> (row tid>>1, word half (tid&1)*8) ----
    const int lr = tid >> 1;
    const int lw = (tid & 1) * 8;
    size_t rowA;
    {
        int ar = m0 + lr;
        if (MODE == 0) rowA = ar;
        else {
            int idx = ar < Me ? ar : Me - 1;
            rowA = (MODE == 1) ? (size_t)tokl[e * Tt + idx] : (size_t)(hbase + idx);
        }
    }
    const uint32_t* pah = Ahp + rowA * KW + lw;
    const uint32_t* pal = pah + aLoOff;
    const uint32_t* pbh = Bh_e + (size_t)(n0 + lr) * KW + lw;
    const uint32_t* pbl = pbh + bLoOff;

    const uint32_t sbase = (uint32_t)__cvta_generic_to_shared(dsm);
    const uint32_t dw = (uint32_t)(lr * 20 + lw) * 4;

#define ISSUE_TILE(buf) do {                                    \
        uint32_t d = sbase + (buf) * 40960u + dw;               \
        CP_ASYNC16(d,                pah);                      \
        CP_ASYNC16(d + 16,           pah + 4);                  \
        CP_ASYNC16(d + 10240u,       pal);                      \
        CP_ASYNC16(d + 10240u + 16,  pal + 4);                  \
        CP_ASYNC16(d + 20480u,       pbh);                      \
        CP_ASYNC16(d + 20480u + 16,  pbh + 4);                  \
        CP_ASYNC16(d + 30720u,       pbl);                      \
        CP_ASYNC16(d + 30720u + 16,  pbl + 4);                  \
        pah += 16; pal += 16; pbh += 16; pbl += 16;             \
        CP_COMMIT();                                            \
    } while (0)

    // ldmatrix per-lane base addresses (pitch 20 words, conflict-free)
    const uint32_t aB = sbase +
        (uint32_t)(((wm * 64 + (lane & 15)) * 20 + (lane >> 4) * 4) * 4);
    const uint32_t bB = sbase + 20480u +
        (uint32_t)(((wn * 32 + (lane & 7)) * 20 + ((lane >> 3) & 1) * 4) * 4);

    float acc[4][4][4];
    #pragma unroll
    for (int i = 0; i < 4; i++)
        #pragma unroll
        for (int j = 0; j < 4; j++)
            #pragma unroll
            for (int q = 0; q < 4; q++) acc[i][j][q] = 0.f;

    const int ktiles = Kd / 32;

    ISSUE_TILE(0);

    for (int t = 0; t < ktiles; t++) {
        const int cur = t & 1;
        if (t + 1 < ktiles) {
            ISSUE_TILE((t + 1) & 1);
            asm volatile("cp.async.wait_group 1;");
        } else {
            asm volatile("cp.async.wait_group 0;");
        }
        __syncthreads();

        const uint32_t bufB = cur * 40960u;
        #pragma unroll
        for (int ks = 0; ks < 2; ks++) {
            uint32_t ah[4][4], al[4][4];
            #pragma unroll
            for (int i = 0; i < 4; i++) {
                const uint32_t ao = aB + bufB + (uint32_t)((i * 320 + ks * 8) * 4);
                ldsm_x4(ah[i][0], ah[i][1], ah[i][2], ah[i][3], ao);
                ldsm_x4(al[i][0], al[i][1], al[i][2], al[i][3], ao + 10240u);
            }
            #pragma unroll
            for (int j = 0; j < 4; j++) {
                const uint32_t bo = bB + bufB + (uint32_t)((j * 160 + ks * 8) * 4);
                uint32_t b0h, b1h, b0l, b1l;
                ldsm_x2(b0h, b1h, bo);
                ldsm_x2(b0l, b1l, bo + 10240u);
                #pragma unroll
                for (int i = 0; i < 4; i++) {
                    mma_bf16(acc[i][j], ah[i][0], ah[i][1], ah[i][2], ah[i][3], b0h, b1h);
                    mma_bf16(acc[i][j], ah[i][0], ah[i][1], ah[i][2], ah[i][3], b0l, b1l);
                    mma_bf16(acc[i][j], al[i][0], al[i][1], al[i][2], al[i][3], b0h, b1h);
                }
            }
        }
        __syncthreads();
    }
#undef ISSUE_TILE

    // ---- epilogue ----
    uint32_t* chh = (uint32_t*)C;
    uint32_t* chl = chh + (size_t)Tt * Kk * (Ff / 2);
    #pragma unroll
    for (int i = 0; i < 4; i++) {
        const int r = m0 + wm * 64 + i * 16 + tr;
        #pragma unroll
        for (int j = 0; j < 4; j++) {
            const int c = n0 + wn * 32 + j * 8 + tc * 2;
            const float b0 = bp[c], b1 = bp[c + 1];
            if (MODE == 0) {
                *(float2*)&C[(size_t)r * N + c] =
                    make_float2(acc[i][j][0] + b0, acc[i][j][1] + b1);
                *(float2*)&C[(size_t)(r + 8) * N + c] =
                    make_float2(acc[i][j][2] + b0, acc[i][j][3] + b1);
            } else if (MODE == 1) {
                if (r < Me) {
                    float v0 = acc[i][j][0] + b0, v1 = acc[i][j][1] + b1;
                    float g0 = 0.5f * v0 * (1.0f + erff(v0 * 0.7071067811865475f));
                    float g1 = 0.5f * v1 * (1.0f + erff(v1 * 0.7071067811865475f));
                    uint32_t hi, lo;
                    split2(g0, g1, hi, lo);
                    chh[(size_t)(hbase + r) * (N / 2) + (c >> 1)] = hi;
                    chl[(size_t)(hbase + r) * (N / 2) + (c >> 1)] = lo;
                }
                if (r + 8 < Me) {
                    float v0 = acc[i][j][2] + b0, v1 = acc[i][j][3] + b1;
                    float g0 = 0.5f * v0 * (1.0f + erff(v0 * 0.7071067811865475f));
                    float g1 = 0.5f * v1 * (1.0f + erff(v1 * 0.7071067811865475f));
                    uint32_t hi, lo;
                    split2(g0, g1, hi, lo);
                    chh[(size_t)(hbase + r + 8) * (N / 2) + (c >> 1)] = hi;
                    chl[(size_t)(hbase + r + 8) * (N / 2) + (c >> 1)] = lo;
                }
            } else {
                if (r < Me) {
                    int   tk = tokl[e * Tt + r];
                    float w  = wtl [e * Tt + r];
                    float* Crow = &C[(size_t)tk * N + c];
                    atomicAdd(&Crow[0], w * (acc[i][j][0] + b0));
                    atomicAdd(&Crow[1], w * (acc[i][j][1] + b1));
                }
                if (r + 8 < Me) {
                    int   tk = tokl[e * Tt + r + 8];
                    float w  = wtl [e * Tt + r + 8];
                    float* Crow = &C[(size_t)tk * N + c];
                    atomicAdd(&Crow[0], w * (acc[i][j][2] + b0));
                    atomicAdd(&Crow[1], w * (acc[i][j][3] + b1));
                }
            }
        }
    }
}

// ------------------------- tensor-core flash attention ---------------------
#define KPITCH 36
#define VPITCH 72

__global__ __launch_bounds__(128)
void attn_tc(const float* __restrict__ q, const float* __restrict__ k,
             const float* __restrict__ v, uint32_t* __restrict__ attc)
{
    const int bh = blockIdx.y;
    const int b = bh >> 4, h = bh & 15;
    const int warp = threadIdx.x >> 5, lane = threadIdx.x & 31;
    const int tr = lane >> 2, tc = lane & 3;
    const int qrow = blockIdx.x * 64 + warp * 16;

    __shared__ uint32_t Kh[64][KPITCH], Kl[64][KPITCH];
    __shared__ uint32_t Vh[32][VPITCH], Vl[32][VPITCH];

    uint32_t qh[4][4], ql[4][4];
    {
        const float* q0 = q + ((size_t)(b * Sq + qrow + tr) * Dm + h * HDIM);
        const float* q1 = q0 + 8 * Dm;
        #pragma unroll
        for (int ks = 0; ks < 4; ks++) {
            int d = ks * 16 + 2 * tc;
            float2 x = *(const float2*)(q0 + d);
            float2 y = *(const float2*)(q1 + d);
            float2 z = *(const float2*)(q0 + d + 8);
            float2 w = *(const float2*)(q1 + d + 8);
            split2(x.x * 0.125f, x.y * 0.125f, qh[ks][0], ql[ks][0]);
            split2(y.x * 0.125f, y.y * 0.125f, qh[ks][1], ql[ks][1]);
            split2(z.x * 0.125f, z.y * 0.125f, qh[ks][2], ql[ks][2]);
            split2(w.x * 0.125f, w.y * 0.125f, qh[ks][3], ql[ks][3]);
        }
    }

    float o[8][4];
    #pragma unroll
    for (int j = 0; j < 8; j++)
        #pragma unroll
        for (int qq = 0; qq < 4; qq++) o[j][qq] = 0.f;
    float m0 = -1e30f, m1 = -1e30f, l0 = 0.f, l1 = 0.f;

    for (int t0 = 0; t0 < Sq; t0 += 64) {
        __syncthreads();
        for (int i = threadIdx.x; i < 64 * 16; i += 128) {
            int row = i >> 4, c4 = (i & 15) * 4;
            float4 kv = *(const float4*)(k + (size_t)(b * Sq + t0 + row) * Dm
                                           + h * HDIM + c4);
            uint32_t h0, l0_, h1, l1_;
            split2(kv.x, kv.y, h0, l0_);
            split2(kv.z, kv.w, h1, l1_);
            *(uint2*)&Kh[row][c4 >> 1] = make_uint2(h0, h1);
            *(uint2*)&Kl[row][c4 >> 1] = make_uint2(l0_, l1_);
        }
        for (int i = threadIdx.x; i < 32 * 16; i += 128) {
            int kk = i >> 4, c4 = (i & 15) * 4;
            const float* vp = v + (size_t)(b * Sq + t0 + 2 * kk) * Dm
                                + h * HDIM + c4;
            float4 r0 = *(const float4*)vp;
            float4 r1 = *(const float4*)(vp + Dm);
            uint32_t hh0, ll0, hh1, ll1, hh2, ll2, hh3, ll3;
            split2(r0.x, r1.x, hh0, ll0);
            split2(r0.y, r1.y, hh1, ll1);
            split2(r0.z, r1.z, hh2, ll2);
            split2(r0.w, r1.w, hh3, ll3);
            *(uint4*)&Vh[kk][c4] = make_uint4(hh0, hh1, hh2, hh3);
            *(uint4*)&Vl[kk][c4] = make_uint4(ll0, ll1, ll2, ll3);
        }
        __syncthreads();

        float sc[8][4];
        #pragma unroll
        for (int j = 0; j < 8; j++) {
            float c[4] = {0.f, 0.f, 0.f, 0.f};
            const int n = j * 8 + tr;
            #pragma unroll
            for (int ks = 0; ks < 4; ks++) {
                uint32_t b0h = Kh[n][8 * ks + tc],     b1h = Kh[n][8 * ks + 4 + tc];
                uint32_t b0l = Kl[n][8 * ks + tc],     b1l = Kl[n][8 * ks + 4 + tc];
                mma_bf16(c, qh[ks][0], qh[ks][1], qh[ks][2], qh[ks][3], b0h, b1h);
                mma_bf16(c, qh[ks][0], qh[ks][1], qh[ks][2], qh[ks][3], b0l, b1l);
                mma_bf16(c, ql[ks][0], ql[ks][1], ql[ks][2], ql[ks][3], b0h, b1h);
            }
            sc[j][0] = c[0]; sc[j][1] = c[1]; sc[j][2] = c[2]; sc[j][3] = c[3];
        }

        float mt0 = -1e30f, mt1 = -1e30f;
        #pragma unroll
        for (int j = 0; j < 8; j++) {
            mt0 = fmaxf(mt0, fmaxf(sc[j][0], sc[j][1]));
            mt1 = fmaxf(mt1, fmaxf(sc[j][2], sc[j][3]));
        }
        mt0 = fmaxf(mt0, __shfl_xor_sync(0xffffffffu, mt0, 1));
        mt0 = fmaxf(mt0, __shfl_xor_sync(0xffffffffu, mt0, 2));
        mt1 = fmaxf(mt1, __shfl_xor_sync(0xffffffffu, mt1, 1));
        mt1 = fmaxf(mt1, __shfl_xor_sync(0xffffffffu, mt1, 2));

        float mn0 = fmaxf(m0, mt0), mn1 = fmaxf(m1, mt1);
        float a0 = __expf(m0 - mn0), a1 = __expf(m1 - mn1);
        l0 *= a0; l1 *= a1;
        #pragma unroll
        for (int j = 0; j < 8; j++) {
            o[j][0] *= a0; o[j][1] *= a0;
            o[j][2] *= a1; o[j][3] *= a1;
        }
        m0 = mn0; m1 = mn1;

        #pragma unroll
        for (int j = 0; j < 8; j++) {
            sc[j][0] = __expf(sc[j][0] - m0);
            sc[j][1] = __expf(sc[j][1] - m0);
            sc[j][2] = __expf(sc[j][2] - m1);
            sc[j][3] = __expf(sc[j][3] - m1);
            l0 += sc[j][0] + sc[j][1];
            l1 += sc[j][2] + sc[j][3];
        }

        uint32_t ph[4][4], pl[4][4];
        #pragma unroll
        for (int ks = 0; ks < 4; ks++) {
            split2(sc[2 * ks][0],     sc[2 * ks][1],     ph[ks][0], pl[ks][0]);
            split2(sc[2 * ks][2],     sc[2 * ks][3],     ph[ks][1], pl[ks][1]);
            split2(sc[2 * ks + 1][0], sc[2 * ks + 1][1], ph[ks][2], pl[ks][2]);
            split2(sc[2 * ks + 1][2], sc[2 * ks + 1][3], ph[ks][3], pl[ks][3]);
        }

        #pragma unroll
        for (int jd = 0; jd < 8; jd++) {
            const int d = jd * 8 + tr;
            #pragma unroll
            for (int ks = 0; ks < 4; ks++) {
                uint32_t b0h = Vh[8 * ks + tc][d], b1h = Vh[8 * ks + 4 + tc][d];
                uint32_t b0l = Vl[8 * ks + tc][d], b1l = Vl[8 * ks + 4 + tc][d];
                mma_bf16(o[jd], ph[ks][0], ph[ks][1], ph[ks][2], ph[ks][3], b0h, b1h);
                mma_bf16(o[jd], ph[ks][0], ph[ks][1], ph[ks][2], ph[ks][3], b0l, b1l);
                mma_bf16(o[jd], pl[ks][0], pl[ks][1], pl[ks][2], pl[ks][3], b0h, b1h);
            }
        }
    }

    l0 += __shfl_xor_sync(0xffffffffu, l0, 1);
    l0 += __shfl_xor_sync(0xffffffffu, l0, 2);
    l1 += __shfl_xor_sync(0xffffffffu, l1, 1);
    l1 += __shfl_xor_sync(0xffffffffu, l1, 2);
    float inv0 = 1.f / l0, inv1 = 1.f / l1;

    const size_t loOff = (size_t)Tt * (Dm / 2);
    const size_t row0 = (size_t)(b * Sq + qrow + tr) * (Dm / 2) + h * (HDIM / 2);
    const size_t row1 = row0 + 8 * (Dm / 2);
    #pragma unroll
    for (int jd = 0; jd < 8; jd++) {
        int idx = 4 * jd + tc;
        uint32_t h0, l0w, h1, l1w;
        split2(o[jd][0] * inv0, o[jd][1] * inv0, h0, l0w);
        split2(o[jd][2] * inv1, o[jd][3] * inv1, h1, l1w);
        attc[row0 + idx] = h0; attc[loOff + row0 + idx] = l0w;
        attc[row1 + idx] = h1; attc[loOff + row1 + idx] = l1w;
    }
}

// ------------------------- LayerNorm(a + b) --------------------------------
__global__ __launch_bounds__(256)
void ln_kernel(const float* __restrict__ a, const float* __restrict__ bsrc,
               const float* __restrict__ g, const float* __restrict__ beta,
               float* __restrict__ out, uint32_t* __restrict__ hic)
{
    const int row = blockIdx.x;
    __shared__ float buf[Dm];
    __shared__ float red[8];
    const int tid = threadIdx.x;
    const int lane = tid & 31, wid = tid >> 5;

    float s = 0.f;
    for (int d = tid; d < Dm; d += 256) {
        float v = a[(size_t)row * Dm + d] + bsrc[(size_t)row * Dm + d];
        buf[d] = v;
        s += v;
    }
    #pragma unroll
    for (int o = 16; o; o >>= 1) s += __shfl_xor_sync(0xffffffffu, s, o);
    if (lane == 0) red[wid] = s;
    __syncthreads();
    float mean = (red[0]+red[1]+red[2]+red[3]+red[4]+red[5]+red[6]+red[7]) * (1.f/Dm);

    float s2 = 0.f;
    for (int d = tid; d < Dm; d += 256) {
        float c = buf[d] - mean;
        s2 += c * c;
    }
    #pragma unroll
    for (int o = 16; o; o >>= 1) s2 += __shfl_xor_sync(0xffffffffu, s2, o);
    __syncthreads();
    if (lane == 0) red[wid] = s2;
    __syncthreads();
    float var = (red[0]+red[1]+red[2]+red[3]+red[4]+red[5]+red[6]+red[7]) * (1.f/Dm);
    float rstd = rsqrtf(var + 1e-5f);

    for (int d = tid; d < Dm; d += 256)
        out[(size_t)row * Dm + d] = (buf[d] - mean) * rstd * g[d] + beta[d];

    if (hic) {
        const size_t loOff = (size_t)Tt * (Dm / 2);
        for (int c = tid; c < Dm / 2; c += 256) {
            float y0 = (buf[2 * c]     - mean) * rstd * g[2 * c]     + beta[2 * c];
            float y1 = (buf[2 * c + 1] - mean) * rstd * g[2 * c + 1] + beta[2 * c + 1];
            uint32_t h, l;
            split2(y0, y1, h, l);
            hic[(size_t)row * (Dm / 2) + c] = h;
            hic[loOff + (size_t)row * (Dm / 2) + c] = l;
        }
    }
}

// ------------------------- gating + top-2 routing --------------------------
__global__ __launch_bounds__(128)
void gate_kernel(const float* __restrict__ x1, const float* __restrict__ gW,
                 const float* __restrict__ gb, int* __restrict__ cnt,
                 int* __restrict__ tokl, float* __restrict__ wtl,
                 float* __restrict__ gsum)
{
    const int t = blockIdx.x;
    __shared__ float xs[Dm];
    __shared__ float lg[Ee];
    const int tid = threadIdx.x;
    for (int d = tid; d < Dm; d += 128) xs[d] = x1[(size_t)t * Dm + d];
    __syncthreads();

    const int lane = tid & 31, wid = tid >> 5;
    for (int e = wid; e < Ee; e += 4) {
        float s = 0.f;
        for (int d = lane; d < Dm; d += 32) s += xs[d] * gW[d * Ee + e];
        #pragma unroll
        for (int o = 16; o; o >>= 1) s += __shfl_xor_sync(0xffffffffu, s, o);
        if (lane == 0) lg[e] = s + gb[e];
    }
    __syncthreads();

    if (tid == 0) {
        float mx = lg[0];
        #pragma unroll
        for (int e = 1; e < Ee; e++) mx = fmaxf(mx, lg[e]);
        float sc[Ee];
        float se = 0.f;
        #pragma unroll
        for (int e = 0; e < Ee; e++) { sc[e] = expf(lg[e] - mx); se += sc[e]; }
        float inv = 1.f / se;
        #pragma unroll
        for (int e = 0; e < Ee; e++) sc[e] *= inv;

        int i1 = 0;
        #pragma unroll
        for (int e = 1; e < Ee; e++) if (sc[e] > sc[i1]) i1 = e;
        int i2 = (i1 == 0) ? 1 : 0;
        #pragma unroll
        for (int e = 0; e < Ee; e++) { if (e == i1 || e == i2) continue; if (sc[e] > sc[i2]) i2 = e; }

        float ws = sc[i1] + sc[i2];
        float w1 = sc[i1] / ws, w2 = sc[i2] / ws;
        int p1 = atomicAdd(&cnt[i1], 1); tokl[i1 * Tt + p1] = t; wtl[i1 * Tt + p1] = w1;
        int p2 = atomicAdd(&cnt[i2], 1); tokl[i2 * Tt + p2] = t; wtl[i2 * Tt + p2] = w2;
        #pragma unroll
        for (int e = 0; e < Ee; e++) atomicAdd(&gsum[e], sc[e]);
    }
}

// ------------------------- small helpers -----------------------------------
__global__ void zero_kernel(float* moe, int* cnt, float* gsum)
{
    int i = blockIdx.x * blockDim.x + threadIdx.x;
    int stride = gridDim.x * blockDim.x;
    for (int j = i; j < Tt * Dm; j += stride) moe[j] = 0.f;
    if (i < Ee) { cnt[i] = 0; gsum[i] = 0.f; }
}

__global__ void offsets_kernel(const int* cnt, int* off)
{
    if (threadIdx.x == 0) {
        int s = 0;
        for (int e = 0; e < Ee; e++) { off[e] = s; s += cnt[e]; }
    }
}

__global__ void aux_kernel(const int* cnt, const float* gsum, float* dst)
{
    if (threadIdx.x == 0) {
        float a = 0.f;
        for (int e = 0; e < Ee; e++)
            a += ((float)cnt[e] / (float)(Tt * Kk)) * (gsum[e] / (float)Tt);
        dst[0] = (float)Ee * a;
    }
}

// ------------------------- launch ------------------------------------------
extern "C" void kernel_launch(void* const* d_in, const int* in_sizes, int n_in,
                              void* d_out, int out_size)
{
    const float* x     = (const float*)d_in[0];
    const float* Wq    = (const float*)d_in[1];
    const float* bq    = (const float*)d_in[2];
    const float* Wk    = (const float*)d_in[3];
    const float* bk    = (const float*)d_in[4];
    const float* Wv    = (const float*)d_in[5];
    const float* bv    = (const float*)d_in[6];
    const float* Wo    = (const float*)d_in[7];
    const float* bo    = (const float*)d_in[8];
    const float* g1    = (const float*)d_in[9];
    const float* beta1 = (const float*)d_in[10];
    const float* gateW = (const float*)d_in[11];
    const float* gateb = (const float*)d_in[12];
    const float* eW1   = (const float*)d_in[13];
    const float* eb1   = (const float*)d_in[14];
    const float* eW2   = (const float*)d_in[15];
    const float* eb2   = (const float*)d_in[16];
    const float* g2    = (const float*)d_in[17];
    const float* beta2 = (const float*)d_in[18];
    float* out = (float*)d_out;

    float *pq, *pk, *pv, *pat, *ppr, *px1, *pmoe, *ph, *pwt, *pgs;
    int *ptok, *pcnt, *poff;
    uint32_t *pxc, *px1c, *pwqc, *pwkc, *pwvc, *pwoc, *pw1c, *pw2c;
    cudaGetSymbolAddress((void**)&pq,   g_q);
    cudaGetSymbolAddress((void**)&pk,   g_k);
    cudaGetSymbolAddress((void**)&pv,   g_v);
    cudaGetSymbolAddress((void**)&pat,  g_att);
    cudaGetSymbolAddress((void**)&ppr,  g_prj);
    cudaGetSymbolAddress((void**)&px1,  g_x1);
    cudaGetSymbolAddress((void**)&pmoe, g_moe);
    cudaGetSymbolAddress((void**)&ph,   g_h);
    cudaGetSymbolAddress((void**)&ptok, g_tok);
    cudaGetSymbolAddress((void**)&pwt,  g_wt);
    cudaGetSymbolAddress((void**)&pcnt, g_cnt);
    cudaGetSymbolAddress((void**)&poff, g_off);
    cudaGetSymbolAddress((void**)&pgs,  g_gsum);
    cudaGetSymbolAddress((void**)&pxc,  g_xc);
    cudaGetSymbolAddress((void**)&px1c, g_x1c);
    cudaGetSymbolAddress((void**)&pwqc, g_wqc);
    cudaGetSymbolAddress((void**)&pwkc, g_wkc);
    cudaGetSymbolAddress((void**)&pwvc, g_wvc);
    cudaGetSymbolAddress((void**)&pwoc, g_woc);
    cudaGetSymbolAddress((void**)&pw1c, g_w1c);
    cudaGetSymbolAddress((void**)&pw2c, g_w2c);

    cudaFuncSetAttribute(gemm_tc<0>, cudaFuncAttributeMaxDynamicSharedMemorySize, GSMEM_BYTES);
    cudaFuncSetAttribute(gemm_tc<1>, cudaFuncAttributeMaxDynamicSharedMemorySize, GSMEM_BYTES);
    cudaFuncSetAttribute(gemm_tc<2>, cudaFuncAttributeMaxDynamicSharedMemorySize, GSMEM_BYTES);

    const size_t aLoX  = (size_t)Tt * Dm / 2;                 // activations
    const size_t wLo   = (size_t)Dm * (Dm / 2);               // dense weights
    const size_t w1Lo  = (size_t)Ee * Ff * (Dm / 2);          // eW1 n-major
    const size_t w2Lo  = (size_t)Ee * Dm * (Ff / 2);          // eW2 n-major
    const size_t hLo   = (size_t)Tt * Kk * (Ff / 2);          // packed hidden

    dim3 cb(32, 8);
    dim3 gQ(Dm / 128, Tt / 128, 1);

    // Launch order chosen so ncu's "-s 5 -c 1" captures a GEMM (launch #5).
    conv_rows<<<4096, 256>>>(x, pxc, Tt * Dm);                          // 0
    convT<<<dim3(Dm / 32, Dm / 64, 1), cb>>>(Wq, pwqc, Dm, Dm, wLo);    // 1
    convT<<<dim3(Dm / 32, Dm / 64, 1), cb>>>(Wk, pwkc, Dm, Dm, wLo);    // 2
    convT<<<dim3(Dm / 32, Dm / 64, 1), cb>>>(Wv, pwvc, Dm, Dm, wLo);    // 3

    gemm_tc<0><<<gQ, 256, GSMEM_BYTES>>>(pxc, aLoX, pwqc, wLo, bq, pq,  // 4
        Tt, Dm, Dm, nullptr, nullptr, nullptr, nullptr);
    gemm_tc<0><<<gQ, 256, GSMEM_BYTES>>>(pxc, aLoX, pwkc, wLo, bk, pk,  // 5 (ncu)
        Tt, Dm, Dm, nullptr, nullptr, nullptr, nullptr);
    gemm_tc<0><<<gQ, 256, GSMEM_BYTES>>>(pxc, aLoX, pwvc, wLo, bv, pv,  // 6
        Tt, Dm, Dm, nullptr, nullptr, nullptr, nullptr);

    convT<<<dim3(Dm / 32, Dm / 64, 1), cb>>>(Wo, pwoc, Dm, Dm, wLo);    // 7
    attn_tc<<<dim3(Sq / 64, Bc * Hh), 128>>>(pq, pk, pv, (uint32_t*)pat); // 8

    gemm_tc<0><<<gQ, 256, GSMEM_BYTES>>>((uint32_t*)pat, aLoX, pwoc, wLo, bo, ppr,
        Tt, Dm, Dm, nullptr, nullptr, nullptr, nullptr);
    ln_kernel<<<Tt, 256>>>(x, ppr, g1, beta1, px1, px1c);

    zero_kernel<<<2048, 256>>>(pmoe, pcnt, pgs);
    gate_kernel<<<Tt, 128>>>(px1, gateW, gateb, pcnt, ptok, pwt, pgs);
    offsets_kernel<<<1, 32>>>(pcnt, poff);

    convT<<<dim3(Ff / 32, Dm / 64, Ee), cb>>>(eW1, pw1c, Dm, Ff, w1Lo);
    gemm_tc<1><<<dim3(Ff / 128, Tt / 128, Ee), 256, GSMEM_BYTES>>>(
        px1c, aLoX, pw1c, w1Lo, eb1, ph, Tt, Ff, Dm, pcnt, poff, ptok, pwt);

    convT<<<dim3(Dm / 32, Ff / 64, Ee), cb>>>(eW2, pw2c, Ff, Dm, w2Lo);
    gemm_tc<2><<<dim3(Dm / 128, Tt / 128, Ee), 256, GSMEM_BYTES>>>(
        (uint32_t*)ph, hLo, pw2c, w2Lo, eb2, pmoe, Tt, Dm, Ff, pcnt, poff, ptok, pwt);

    ln_kernel<<<Tt, 256>>>(px1, pmoe, g2, beta2, out, nullptr);

    if (out_size > Tt * Dm)
        aux_kernel<<<1, 32>>>(pcnt, pgs, out + (size_t)Tt * Dm);
}

// round 16
// speedup vs baseline: 1.1364x; 1.1364x over previous
#include <cuda_runtime.h>
#include <math.h>
#include <stdint.h>

#define Bc 4
#define Sq 2048
#define Dm 1024
#define Hh 16
#define HDIM 64
#define Ff 4096
#define Ee 8
#define Kk 2
#define Tt (Bc*Sq)   /* 8192 tokens */

// ------------------------- scratch (device globals; no allocs allowed) ----
__device__ float g_q  [(size_t)Tt*Dm];
__device__ float g_k  [(size_t)Tt*Dm];
__device__ float g_v  [(size_t)Tt*Dm];
__device__ float g_att[(size_t)Tt*Dm];   // bf16 hi/lo planes (cast)
__device__ float g_prj[(size_t)Tt*Dm];
__device__ float g_x1 [(size_t)Tt*Dm];
__device__ float g_moe[(size_t)Tt*Dm];
__device__ float g_h  [(size_t)Tt*Kk*Ff];  // packed hidden as hi/lo planes
__device__ int   g_tok[Ee*Tt];
__device__ float g_wt [Ee*Tt];
__device__ int   g_cnt[Ee];
__device__ int   g_off[Ee];
__device__ float g_gsum[Ee];
// pre-split bf16x2 hi/lo planes (hi plane first, lo plane follows)
__device__ uint32_t g_xc [(size_t)Tt*Dm];
__device__ uint32_t g_x1c[(size_t)Tt*Dm];
__device__ uint32_t g_wqc[(size_t)Dm*Dm];
__device__ uint32_t g_wkc[(size_t)Dm*Dm];
__device__ uint32_t g_wvc[(size_t)Dm*Dm];
__device__ uint32_t g_woc[(size_t)Dm*Dm];
__device__ uint32_t g_w1c[(size_t)Ee*Dm*Ff];
__device__ uint32_t g_w2c[(size_t)Ee*Ff*Dm];

// ------------------------- helpers -----------------------------------------
__device__ __forceinline__ void split2(float x0, float x1,
                                       uint32_t& hi, uint32_t& lo)
{
    uint32_t h;
    asm("cvt.rn.bf16x2.f32 %0, %1, %2;" : "=r"(h) : "f"(x1), "f"(x0));
    float h0 = __uint_as_float(h << 16);
    float h1 = __uint_as_float(h & 0xffff0000u);
    uint32_t l;
    asm("cvt.rn.bf16x2.f32 %0, %1, %2;" : "=r"(l) : "f"(x1 - h1), "f"(x0 - h0));
    hi = h; lo = l;
}

__device__ __forceinline__ void mma_bf16(float c[4],
    uint32_t a0, uint32_t a1, uint32_t a2, uint32_t a3,
    uint32_t b0, uint32_t b1)
{
    asm volatile(
        "mma.sync.aligned.m16n8k16.row.col.f32.bf16.bf16.f32 "
        "{%0,%1,%2,%3}, {%4,%5,%6,%7}, {%8,%9}, {%0,%1,%2,%3};"
        : "+f"(c[0]), "+f"(c[1]), "+f"(c[2]), "+f"(c[3])
        : "r"(a0), "r"(a1), "r"(a2), "r"(a3), "r"(b0), "r"(b1));
}

#define CP_ASYNC16(dst, src) \
    asm volatile("cp.async.cg.shared.global [%0], [%1], 16;" :: "r"(dst), "l"(src))
#define CP_COMMIT() asm volatile("cp.async.commit_group;")

// ------------------------- conversion kernels (vectorized) -----------------
// A-side: pack pairs of consecutive floats -> hi/lo planes (k-major rows).
// float4 in -> uint2 per plane out (2 pairs / thread / iter).
__global__ void conv_rows(const float* __restrict__ src,
                          uint32_t* __restrict__ dst, int n)
{
    int quarter = n >> 2;
    uint2* dh = (uint2*)dst;
    uint2* dl = (uint2*)(dst + (n >> 1));
    for (int i = blockIdx.x * blockDim.x + threadIdx.x; i < quarter;
         i += gridDim.x * blockDim.x) {
        float4 v = ((const float4*)src)[i];
        uint32_t h0, l0, h1, l1;
        split2(v.x, v.y, h0, l0);
        split2(v.z, v.w, h1, l1);
        dh[i] = make_uint2(h0, h1);
        dl[i] = make_uint2(l0, l1);
    }
}

// B-side: pack pairs of rows (k = row index) -> hi/lo planes dst[kp][n].
// 4 columns per thread: float4 reads of both rows, uint4 plane writes.
__global__ void conv_cols4(const float* __restrict__ src,
                           uint32_t* __restrict__ dst, int N, size_t planeElems)
{
    size_t kp = blockIdx.y;
    int n = (blockIdx.x * 256 + threadIdx.x) * 4;
    float4 a = *(const float4*)&src[(size_t)(2 * kp) * N + n];
    float4 b = *(const float4*)&src[(size_t)(2 * kp + 1) * N + n];
    uint4 h, l;
    split2(a.x, b.x, h.x, l.x);
    split2(a.y, b.y, h.y, l.y);
    split2(a.z, b.z, h.z, l.z);
    split2(a.w, b.w, h.w, l.w);
    *(uint4*)&dst[kp * N + n] = h;
    *(uint4*)&dst[planeElems + kp * N + n] = l;
}

// ------------------------- pre-split bf16x3 GEMM ---------------------------
// All operands pre-split in global memory as bf16x2 hi/lo planes (pairs along
// k). 128x128 tile, BK=32, 256 threads (2x4 warps, 64x32 each), double-
// buffered cp.async into dynamic smem; inner loop = pure LDS + MMA (x3).
// MODE 0: C fp32 = A@B + bias.
// MODE 1: A rows gathered via tokl; GELU; out packed hi/lo planes (g_h).
// MODE 2: A = packed h planes; scatter-add w*(acc+bias) into moe[token].
#define GSMEM_BYTES 75776
// smem word layout: Ah[2][128][20] @0, Al @5120, Bh[2][16][136] @10240, Bl @14592

template<int MODE>
__global__ __launch_bounds__(256, 2)
void gemm_tc(const uint32_t* __restrict__ Ahp, size_t aLoOff,
             const uint32_t* __restrict__ Bhp, size_t bLoOff,
             const float* __restrict__ bias,
             float* __restrict__ C,
             int M, int N, int Kd,
             const int* __restrict__ cnt,
             const int* __restrict__ off,
             const int* __restrict__ tokl,
             const float* __restrict__ wtl)
{
    extern __shared__ uint32_t dsm[];

    const int e  = blockIdx.z;
    const int m0 = blockIdx.y * 128;
    const int n0 = blockIdx.x * 128;

    int Me = M, hbase = 0;
    const uint32_t* Bh_e = Bhp;
    const float* bp = bias;
    if (MODE != 0) {
        Me = cnt[e];
        if (m0 >= Me) return;
        Bh_e = Bhp + (size_t)e * (Kd / 2) * N;
        bp = bias + (size_t)e * N;
        hbase = off[e];
    }

    const int tid  = threadIdx.x;
    const int lane = tid & 31, warp = tid >> 5;
    const int wm = warp >> 2, wn = warp & 3;
    const int tr = lane >> 2, tc = lane & 3;

    const int KW = Kd / 2;   // uint32 per A row

    // ---- A loader: chunks tid (row r0a) and tid+256 (row r0a+64) ----
    const int r0a = tid >> 2;
    const int woff_a = (tid & 3) * 4;
    size_t rowA0, rowA1;
    {
        int a0 = m0 + r0a, a1 = m0 + 64 + r0a;
        if (MODE == 0) { rowA0 = a0; rowA1 = a1; }
        else {
            int i0 = a0 < Me ? a0 : Me - 1;
            int i1 = a1 < Me ? a1 : Me - 1;
            if (MODE == 1) { rowA0 = tokl[e * Tt + i0]; rowA1 = tokl[e * Tt + i1]; }
            else           { rowA0 = hbase + i0;        rowA1 = hbase + i1; }
        }
    }
    const uint32_t* pa0h = Ahp + rowA0 * KW + woff_a;
    const uint32_t* pa1h = Ahp + rowA1 * KW + woff_a;
    const uint32_t* pa0l = pa0h + aLoOff;
    const uint32_t* pa1l = pa1h + aLoOff;

    // ---- B loader: chunks tid (pair-row bp0) and tid+256 (bp0+8) ----
    const int bp0 = tid >> 5;
    const int bn0 = (tid & 31) * 4;
    const uint32_t* pb0h = Bh_e + (size_t)bp0 * N + n0 + bn0;
    const uint32_t* pb1h = Bh_e + (size_t)(8 + bp0) * N + n0 + bn0;
    const uint32_t* pb0l = pb0h + bLoOff;
    const uint32_t* pb1l = pb1h + bLoOff;

    const uint32_t sbase = (uint32_t)__cvta_generic_to_shared(dsm);
    const uint32_t dA0 = sbase + (uint32_t)(r0a * 20 + woff_a) * 4;
    const uint32_t dA1 = sbase + (uint32_t)((64 + r0a) * 20 + woff_a) * 4;
    const uint32_t dB0 = sbase + 40960u + (uint32_t)(bp0 * 136 + bn0) * 4;
    const uint32_t dB1 = sbase + 40960u + (uint32_t)((8 + bp0) * 136 + bn0) * 4;

#define ISSUE_TILE(buf) do {                                   \
        CP_ASYNC16(dA0 + (buf) * 10240u, pa0h);                \
        CP_ASYNC16(dA1 + (buf) * 10240u, pa1h);                \
        CP_ASYNC16(dA0 + 20480u + (buf) * 10240u, pa0l);       \
        CP_ASYNC16(dA1 + 20480u + (buf) * 10240u, pa1l);       \
        CP_ASYNC16(dB0 + (buf) * 8704u,  pb0h);                \
        CP_ASYNC16(dB1 + (buf) * 8704u,  pb1h);                \
        CP_ASYNC16(dB0 + 17408u + (buf) * 8704u, pb0l);        \
        CP_ASYNC16(dB1 + 17408u + (buf) * 8704u, pb1l);        \
        pa0h += 16; pa1h += 16; pa0l += 16; pa1l += 16;        \
        pb0h += (size_t)16 * N; pb1h += (size_t)16 * N;        \
        pb0l += (size_t)16 * N; pb1l += (size_t)16 * N;        \
        CP_COMMIT();                                           \
    } while (0)

    float acc[4][4][4];
    #pragma unroll
    for (int i = 0; i < 4; i++)
        #pragma unroll
        for (int j = 0; j < 4; j++)
            #pragma unroll
            for (int q = 0; q < 4; q++) acc[i][j][q] = 0.f;

    const int ktiles = Kd / 32;

    ISSUE_TILE(0);

    for (int t = 0; t < ktiles; t++) {
        const int cur = t & 1;
        if (t + 1 < ktiles) {
            ISSUE_TILE((t + 1) & 1);
            asm volatile("cp.async.wait_group 1;");
        } else {
            asm volatile("cp.async.wait_group 0;");
        }
        __syncthreads();

        const uint32_t* Ah = dsm + cur * 2560;
        const uint32_t* Al = dsm + 5120 + cur * 2560;
        const uint32_t* Bh = dsm + 10240 + cur * 2176;
        const uint32_t* Bl = dsm + 14592 + cur * 2176;

        #pragma unroll
        for (int ks = 0; ks < 2; ks++) {
            uint32_t ah[4][4], al[4][4];
            #pragma unroll
            for (int i = 0; i < 4; i++) {
                const int r = (wm * 64 + i * 16 + tr) * 20 + 8 * ks + tc;
                ah[i][0] = Ah[r];
                ah[i][1] = Ah[r + 8 * 20];
                ah[i][2] = Ah[r + 4];
                ah[i][3] = Ah[r + 8 * 20 + 4];
                al[i][0] = Al[r];
                al[i][1] = Al[r + 8 * 20];
                al[i][2] = Al[r + 4];
                al[i][3] = Al[r + 8 * 20 + 4];
            }
            #pragma unroll
            for (int j = 0; j < 4; j++) {
                const int n = wn * 32 + j * 8 + tr;
                const uint32_t b0h = Bh[(8 * ks + tc) * 136 + n];
                const uint32_t b1h = Bh[(8 * ks + 4 + tc) * 136 + n];
                const uint32_t b0l = Bl[(8 * ks + tc) * 136 + n];
                const uint32_t b1l = Bl[(8 * ks + 4 + tc) * 136 + n];
                #pragma unroll
                for (int i = 0; i < 4; i++) {
                    mma_bf16(acc[i][j], ah[i][0], ah[i][1], ah[i][2], ah[i][3], b0h, b1h);
                    mma_bf16(acc[i][j], ah[i][0], ah[i][1], ah[i][2], ah[i][3], b0l, b1l);
                    mma_bf16(acc[i][j], al[i][0], al[i][1], al[i][2], al[i][3], b0h, b1h);
                }
            }
        }
        __syncthreads();
    }
#undef ISSUE_TILE

    // ---- epilogue ----
    uint32_t* chh = (uint32_t*)C;
    uint32_t* chl = chh + (size_t)Tt * Kk * (Ff / 2);
    #pragma unroll
    for (int i = 0; i < 4; i++) {
        const int r = m0 + wm * 64 + i * 16 + tr;
        #pragma unroll
        for (int j = 0; j < 4; j++) {
            const int c = n0 + wn * 32 + j * 8 + tc * 2;
            const float b0 = bp[c], b1 = bp[c + 1];
            if (MODE == 0) {
                *(float2*)&C[(size_t)r * N + c] =
                    make_float2(acc[i][j][0] + b0, acc[i][j][1] + b1);
                *(float2*)&C[(size_t)(r + 8) * N + c] =
                    make_float2(acc[i][j][2] + b0, acc[i][j][3] + b1);
            } else if (MODE == 1) {
                if (r < Me) {
                    float v0 = acc[i][j][0] + b0, v1 = acc[i][j][1] + b1;
                    float g0 = 0.5f * v0 * (1.0f + erff(v0 * 0.7071067811865475f));
                    float g1 = 0.5f * v1 * (1.0f + erff(v1 * 0.7071067811865475f));
                    uint32_t hi, lo;
                    split2(g0, g1, hi, lo);
                    chh[(size_t)(hbase + r) * (N / 2) + (c >> 1)] = hi;
                    chl[(size_t)(hbase + r) * (N / 2) + (c >> 1)] = lo;
                }
                if (r + 8 < Me) {
                    float v0 = acc[i][j][2] + b0, v1 = acc[i][j][3] + b1;
                    float g0 = 0.5f * v0 * (1.0f + erff(v0 * 0.7071067811865475f));
                    float g1 = 0.5f * v1 * (1.0f + erff(v1 * 0.7071067811865475f));
                    uint32_t hi, lo;
                    split2(g0, g1, hi, lo);
                    chh[(size_t)(hbase + r + 8) * (N / 2) + (c >> 1)] = hi;
                    chl[(size_t)(hbase + r + 8) * (N / 2) + (c >> 1)] = lo;
                }
            } else {
                if (r < Me) {
                    int   tk = tokl[e * Tt + r];
                    float w  = wtl [e * Tt + r];
                    float* Crow = &C[(size_t)tk * N + c];
                    atomicAdd(&Crow[0], w * (acc[i][j][0] + b0));
                    atomicAdd(&Crow[1], w * (acc[i][j][1] + b1));
                }
                if (r + 8 < Me) {
                    int   tk = tokl[e * Tt + r + 8];
                    float w  = wtl [e * Tt + r + 8];
                    float* Crow = &C[(size_t)tk * N + c];
                    atomicAdd(&Crow[0], w * (acc[i][j][2] + b0));
                    atomicAdd(&Crow[1], w * (acc[i][j][3] + b1));
                }
            }
        }
    }
}

// ------------------------- tensor-core flash attention ---------------------
#define KPITCH 36
#define VPITCH 72

__global__ __launch_bounds__(128)
void attn_tc(const float* __restrict__ q, const float* __restrict__ k,
             const float* __restrict__ v, uint32_t* __restrict__ attc)
{
    const int bh = blockIdx.y;
    const int b = bh >> 4, h = bh & 15;
    const int warp = threadIdx.x >> 5, lane = threadIdx.x & 31;
    const int tr = lane >> 2, tc = lane & 3;
    const int qrow = blockIdx.x * 64 + warp * 16;

    __shared__ uint32_t Kh[64][KPITCH], Kl[64][KPITCH];
    __shared__ uint32_t Vh[32][VPITCH], Vl[32][VPITCH];

    uint32_t qh[4][4], ql[4][4];
    {
        const float* q0 = q + ((size_t)(b * Sq + qrow + tr) * Dm + h * HDIM);
        const float* q1 = q0 + 8 * Dm;
        #pragma unroll
        for (int ks = 0; ks < 4; ks++) {
            int d = ks * 16 + 2 * tc;
            float2 x = *(const float2*)(q0 + d);
            float2 y = *(const float2*)(q1 + d);
            float2 z = *(const float2*)(q0 + d + 8);
            float2 w = *(const float2*)(q1 + d + 8);
            split2(x.x * 0.125f, x.y * 0.125f, qh[ks][0], ql[ks][0]);
            split2(y.x * 0.125f, y.y * 0.125f, qh[ks][1], ql[ks][1]);
            split2(z.x * 0.125f, z.y * 0.125f, qh[ks][2], ql[ks][2]);
            split2(w.x * 0.125f, w.y * 0.125f, qh[ks][3], ql[ks][3]);
        }
    }

    float o[8][4];
    #pragma unroll
    for (int j = 0; j < 8; j++)
        #pragma unroll
        for (int qq = 0; qq < 4; qq++) o[j][qq] = 0.f;
    float m0 = -1e30f, m1 = -1e30f, l0 = 0.f, l1 = 0.f;

    for (int t0 = 0; t0 < Sq; t0 += 64) {
        __syncthreads();
        for (int i = threadIdx.x; i < 64 * 16; i += 128) {
            int row = i >> 4, c4 = (i & 15) * 4;
            float4 kv = *(const float4*)(k + (size_t)(b * Sq + t0 + row) * Dm
                                           + h * HDIM + c4);
            uint32_t h0, l0_, h1, l1_;
            split2(kv.x, kv.y, h0, l0_);
            split2(kv.z, kv.w, h1, l1_);
            *(uint2*)&Kh[row][c4 >> 1] = make_uint2(h0, h1);
            *(uint2*)&Kl[row][c4 >> 1] = make_uint2(l0_, l1_);
        }
        for (int i = threadIdx.x; i < 32 * 16; i += 128) {
            int kk = i >> 4, c4 = (i & 15) * 4;
            const float* vp = v + (size_t)(b * Sq + t0 + 2 * kk) * Dm
                                + h * HDIM + c4;
            float4 r0 = *(const float4*)vp;
            float4 r1 = *(const float4*)(vp + Dm);
            uint32_t hh0, ll0, hh1, ll1, hh2, ll2, hh3, ll3;
            split2(r0.x, r1.x, hh0, ll0);
            split2(r0.y, r1.y, hh1, ll1);
            split2(r0.z, r1.z, hh2, ll2);
            split2(r0.w, r1.w, hh3, ll3);
            *(uint4*)&Vh[kk][c4] = make_uint4(hh0, hh1, hh2, hh3);
            *(uint4*)&Vl[kk][c4] = make_uint4(ll0, ll1, ll2, ll3);
        }
        __syncthreads();

        float sc[8][4];
        #pragma unroll
        for (int j = 0; j < 8; j++) {
            float c[4] = {0.f, 0.f, 0.f, 0.f};
            const int n = j * 8 + tr;
            #pragma unroll
            for (int ks = 0; ks < 4; ks++) {
                uint32_t b0h = Kh[n][8 * ks + tc],     b1h = Kh[n][8 * ks + 4 + tc];
                uint32_t b0l = Kl[n][8 * ks + tc],     b1l = Kl[n][8 * ks + 4 + tc];
                mma_bf16(c, qh[ks][0], qh[ks][1], qh[ks][2], qh[ks][3], b0h, b1h);
                mma_bf16(c, qh[ks][0], qh[ks][1], qh[ks][2], qh[ks][3], b0l, b1l);
                mma_bf16(c, ql[ks][0], ql[ks][1], ql[ks][2], ql[ks][3], b0h, b1h);
            }
            sc[j][0] = c[0]; sc[j][1] = c[1]; sc[j][2] = c[2]; sc[j][3] = c[3];
        }

        float mt0 = -1e30f, mt1 = -1e30f;
        #pragma unroll
        for (int j = 0; j < 8; j++) {
            mt0 = fmaxf(mt0, fmaxf(sc[j][0], sc[j][1]));
            mt1 = fmaxf(mt1, fmaxf(sc[j][2], sc[j][3]));
        }
        mt0 = fmaxf(mt0, __shfl_xor_sync(0xffffffffu, mt0, 1));
        mt0 = fmaxf(mt0, __shfl_xor_sync(0xffffffffu, mt0, 2));
        mt1 = fmaxf(mt1, __shfl_xor_sync(0xffffffffu, mt1, 1));
        mt1 = fmaxf(mt1, __shfl_xor_sync(0xffffffffu, mt1, 2));

        float mn0 = fmaxf(m0, mt0), mn1 = fmaxf(m1, mt1);
        float a0 = __expf(m0 - mn0), a1 = __expf(m1 - mn1);
        l0 *= a0; l1 *= a1;
        #pragma unroll
        for (int j = 0; j < 8; j++) {
            o[j][0] *= a0; o[j][1] *= a0;
            o[j][2] *= a1; o[j][3] *= a1;
        }
        m0 = mn0; m1 = mn1;

        #pragma unroll
        for (int j = 0; j < 8; j++) {
            sc[j][0] = __expf(sc[j][0] - m0);
            sc[j][1] = __expf(sc[j][1] - m0);
            sc[j][2] = __expf(sc[j][2] - m1);
            sc[j][3] = __expf(sc[j][3] - m1);
            l0 += sc[j][0] + sc[j][1];
            l1 += sc[j][2] + sc[j][3];
        }

        uint32_t ph[4][4], pl[4][4];
        #pragma unroll
        for (int ks = 0; ks < 4; ks++) {
            split2(sc[2 * ks][0],     sc[2 * ks][1],     ph[ks][0], pl[ks][0]);
            split2(sc[2 * ks][2],     sc[2 * ks][3],     ph[ks][1], pl[ks][1]);
            split2(sc[2 * ks + 1][0], sc[2 * ks + 1][1], ph[ks][2], pl[ks][2]);
            split2(sc[2 * ks + 1][2], sc[2 * ks + 1][3], ph[ks][3], pl[ks][3]);
        }

        #pragma unroll
        for (int jd = 0; jd < 8; jd++) {
            const int d = jd * 8 + tr;
            #pragma unroll
            for (int ks = 0; ks < 4; ks++) {
                uint32_t b0h = Vh[8 * ks + tc][d], b1h = Vh[8 * ks + 4 + tc][d];
                uint32_t b0l = Vl[8 * ks + tc][d], b1l = Vl[8 * ks + 4 + tc][d];
                mma_bf16(o[jd], ph[ks][0], ph[ks][1], ph[ks][2], ph[ks][3], b0h, b1h);
                mma_bf16(o[jd], ph[ks][0], ph[ks][1], ph[ks][2], ph[ks][3], b0l, b1l);
                mma_bf16(o[jd], pl[ks][0], pl[ks][1], pl[ks][2], pl[ks][3], b0h, b1h);
            }
        }
    }

    l0 += __shfl_xor_sync(0xffffffffu, l0, 1);
    l0 += __shfl_xor_sync(0xffffffffu, l0, 2);
    l1 += __shfl_xor_sync(0xffffffffu, l1, 1);
    l1 += __shfl_xor_sync(0xffffffffu, l1, 2);
    float inv0 = 1.f / l0, inv1 = 1.f / l1;

    const size_t loOff = (size_t)Tt * (Dm / 2);
    const size_t row0 = (size_t)(b * Sq + qrow + tr) * (Dm / 2) + h * (HDIM / 2);
    const size_t row1 = row0 + 8 * (Dm / 2);
    #pragma unroll
    for (int jd = 0; jd < 8; jd++) {
        int idx = 4 * jd + tc;
        uint32_t h0, l0w, h1, l1w;
        split2(o[jd][0] * inv0, o[jd][1] * inv0, h0, l0w);
        split2(o[jd][2] * inv1, o[jd][3] * inv1, h1, l1w);
        attc[row0 + idx] = h0; attc[loOff + row0 + idx] = l0w;
        attc[row1 + idx] = h1; attc[loOff + row1 + idx] = l1w;
    }
}

// ------------------------- LayerNorm(a + b) --------------------------------
__global__ __launch_bounds__(256)
void ln_kernel(const float* __restrict__ a, const float* __restrict__ bsrc,
               const float* __restrict__ g, const float* __restrict__ beta,
               float* __restrict__ out, uint32_t* __restrict__ hic)
{
    const int row = blockIdx.x;
    __shared__ float buf[Dm];
    __shared__ float red[8];
    const int tid = threadIdx.x;
    const int lane = tid & 31, wid = tid >> 5;

    float s = 0.f;
    for (int d = tid; d < Dm; d += 256) {
        float v = a[(size_t)row * Dm + d] + bsrc[(size_t)row * Dm + d];
        buf[d] = v;
        s += v;
    }
    #pragma unroll
    for (int o = 16; o; o >>= 1) s += __shfl_xor_sync(0xffffffffu, s, o);
    if (lane == 0) red[wid] = s;
    __syncthreads();
    float mean = (red[0]+red[1]+red[2]+red[3]+red[4]+red[5]+red[6]+red[7]) * (1.f/Dm);

    float s2 = 0.f;
    for (int d = tid; d < Dm; d += 256) {
        float c = buf[d] - mean;
        s2 += c * c;
    }
    #pragma unroll
    for (int o = 16; o; o >>= 1) s2 += __shfl_xor_sync(0xffffffffu, s2, o);
    __syncthreads();
    if (lane == 0) red[wid] = s2;
    __syncthreads();
    float var = (red[0]+red[1]+red[2]+red[3]+red[4]+red[5]+red[6]+red[7]) * (1.f/Dm);
    float rstd = rsqrtf(var + 1e-5f);

    for (int d = tid; d < Dm; d += 256)
        out[(size_t)row * Dm + d] = (buf[d] - mean) * rstd * g[d] + beta[d];

    if (hic) {
        const size_t loOff = (size_t)Tt * (Dm / 2);
        for (int c = tid; c < Dm / 2; c += 256) {
            float y0 = (buf[2 * c]     - mean) * rstd * g[2 * c]     + beta[2 * c];
            float y1 = (buf[2 * c + 1] - mean) * rstd * g[2 * c + 1] + beta[2 * c + 1];
            uint32_t h, l;
            split2(y0, y1, h, l);
            hic[(size_t)row * (Dm / 2) + c] = h;
            hic[loOff + (size_t)row * (Dm / 2) + c] = l;
        }
    }
}

// ------------------------- gating + top-2 routing --------------------------
__global__ __launch_bounds__(128)
void gate_kernel(const float* __restrict__ x1, const float* __restrict__ gW,
                 const float* __restrict__ gb, int* __restrict__ cnt,
                 int* __restrict__ tokl, float* __restrict__ wtl,
                 float* __restrict__ gsum)
{
    const int t = blockIdx.x;
    __shared__ float xs[Dm];
    __shared__ float lg[Ee];
    const int tid = threadIdx.x;
    for (int d = tid; d < Dm; d += 128) xs[d] = x1[(size_t)t * Dm + d];
    __syncthreads();

    const int lane = tid & 31, wid = tid >> 5;
    for (int e = wid; e < Ee; e += 4) {
        float s = 0.f;
        for (int d = lane; d < Dm; d += 32) s += xs[d] * gW[d * Ee + e];
        #pragma unroll
        for (int o = 16; o; o >>= 1) s += __shfl_xor_sync(0xffffffffu, s, o);
        if (lane == 0) lg[e] = s + gb[e];
    }
    __syncthreads();

    if (tid == 0) {
        float mx = lg[0];
        #pragma unroll
        for (int e = 1; e < Ee; e++) mx = fmaxf(mx, lg[e]);
        float sc[Ee];
        float se = 0.f;
        #pragma unroll
        for (int e = 0; e < Ee; e++) { sc[e] = expf(lg[e] - mx); se += sc[e]; }
        float inv = 1.f / se;
        #pragma unroll
        for (int e = 0; e < Ee; e++) sc[e] *= inv;

        int i1 = 0;
        #pragma unroll
        for (int e = 1; e < Ee; e++) if (sc[e] > sc[i1]) i1 = e;
        int i2 = (i1 == 0) ? 1 : 0;
        #pragma unroll
        for (int e = 0; e < Ee; e++) { if (e == i1 || e == i2) continue; if (sc[e] > sc[i2]) i2 = e; }

        float ws = sc[i1] + sc[i2];
        float w1 = sc[i1] / ws, w2 = sc[i2] / ws;
        int p1 = atomicAdd(&cnt[i1], 1); tokl[i1 * Tt + p1] = t; wtl[i1 * Tt + p1] = w1;
        int p2 = atomicAdd(&cnt[i2], 1); tokl[i2 * Tt + p2] = t; wtl[i2 * Tt + p2] = w2;
        #pragma unroll
        for (int e = 0; e < Ee; e++) atomicAdd(&gsum[e], sc[e]);
    }
}

// ------------------------- small helpers -----------------------------------
__global__ void zero_kernel(float* moe, int* cnt, float* gsum)
{
    int i = blockIdx.x * blockDim.x + threadIdx.x;
    int stride = gridDim.x * blockDim.x;
    for (int j = i; j < Tt * Dm; j += stride) moe[j] = 0.f;
    if (i < Ee) { cnt[i] = 0; gsum[i] = 0.f; }
}

__global__ void offsets_kernel(const int* cnt, int* off)
{
    if (threadIdx.x == 0) {
        int s = 0;
        for (int e = 0; e < Ee; e++) { off[e] = s; s += cnt[e]; }
    }
}

__global__ void aux_kernel(const int* cnt, const float* gsum, float* dst)
{
    if (threadIdx.x == 0) {
        float a = 0.f;
        for (int e = 0; e < Ee; e++)
            a += ((float)cnt[e] / (float)(Tt * Kk)) * (gsum[e] / (float)Tt);
        dst[0] = (float)Ee * a;
    }
}

// ------------------------- launch ------------------------------------------
extern "C" void kernel_launch(void* const* d_in, const int* in_sizes, int n_in,
                              void* d_out, int out_size)
{
    const float* x     = (const float*)d_in[0];
    const float* Wq    = (const float*)d_in[1];
    const float* bq    = (const float*)d_in[2];
    const float* Wk    = (const float*)d_in[3];
    const float* bk    = (const float*)d_in[4];
    const float* Wv    = (const float*)d_in[5];
    const float* bv    = (const float*)d_in[6];
    const float* Wo    = (const float*)d_in[7];
    const float* bo    = (const float*)d_in[8];
    const float* g1    = (const float*)d_in[9];
    const float* beta1 = (const float*)d_in[10];
    const float* gateW = (const float*)d_in[11];
    const float* gateb = (const float*)d_in[12];
    const float* eW1   = (const float*)d_in[13];
    const float* eb1   = (const float*)d_in[14];
    const float* eW2   = (const float*)d_in[15];
    const float* eb2   = (const float*)d_in[16];
    const float* g2    = (const float*)d_in[17];
    const float* beta2 = (const float*)d_in[18];
    float* out = (float*)d_out;

    float *pq, *pk, *pv, *pat, *ppr, *px1, *pmoe, *ph, *pwt, *pgs;
    int *ptok, *pcnt, *poff;
    uint32_t *pxc, *px1c, *pwqc, *pwkc, *pwvc, *pwoc, *pw1c, *pw2c;
    cudaGetSymbolAddress((void**)&pq,   g_q);
    cudaGetSymbolAddress((void**)&pk,   g_k);
    cudaGetSymbolAddress((void**)&pv,   g_v);
    cudaGetSymbolAddress((void**)&pat,  g_att);
    cudaGetSymbolAddress((void**)&ppr,  g_prj);
    cudaGetSymbolAddress((void**)&px1,  g_x1);
    cudaGetSymbolAddress((void**)&pmoe, g_moe);
    cudaGetSymbolAddress((void**)&ph,   g_h);
    cudaGetSymbolAddress((void**)&ptok, g_tok);
    cudaGetSymbolAddress((void**)&pwt,  g_wt);
    cudaGetSymbolAddress((void**)&pcnt, g_cnt);
    cudaGetSymbolAddress((void**)&poff, g_off);
    cudaGetSymbolAddress((void**)&pgs,  g_gsum);
    cudaGetSymbolAddress((void**)&pxc,  g_xc);
    cudaGetSymbolAddress((void**)&px1c, g_x1c);
    cudaGetSymbolAddress((void**)&pwqc, g_wqc);
    cudaGetSymbolAddress((void**)&pwkc, g_wkc);
    cudaGetSymbolAddress((void**)&pwvc, g_wvc);
    cudaGetSymbolAddress((void**)&pwoc, g_woc);
    cudaGetSymbolAddress((void**)&pw1c, g_w1c);
    cudaGetSymbolAddress((void**)&pw2c, g_w2c);

    cudaFuncSetAttribute(gemm_tc<0>, cudaFuncAttributeMaxDynamicSharedMemorySize, GSMEM_BYTES);
    cudaFuncSetAttribute(gemm_tc<1>, cudaFuncAttributeMaxDynamicSharedMemorySize, GSMEM_BYTES);
    cudaFuncSetAttribute(gemm_tc<2>, cudaFuncAttributeMaxDynamicSharedMemorySize, GSMEM_BYTES);

    const size_t aLoX  = (size_t)Tt * Dm / 2;
    const size_t wLo   = (size_t)(Dm / 2) * Dm;
    const size_t w1Lo  = (size_t)Ee * (Dm / 2) * Ff;
    const size_t w2Lo  = (size_t)Ee * (Ff / 2) * Dm;
    const size_t hLo   = (size_t)Tt * Kk * (Ff / 2);

    dim3 gQ(Dm / 128, Tt / 128, 1);

    // ---- operand conversion (vectorized hi/lo bf16 planes) ----
    // Ordered so ncu's "-s 5 -c 1" lands on a gemm_tc launch.
    conv_rows<<<2048, 256>>>(x, pxc, Tt * Dm);                            // 0
    conv_cols4<<<dim3(Dm / 1024, Dm / 2), 256>>>(Wq, pwqc, Dm, wLo);      // 1
    conv_cols4<<<dim3(Dm / 1024, Dm / 2), 256>>>(Wk, pwkc, Dm, wLo);      // 2
    conv_cols4<<<dim3(Dm / 1024, Dm / 2), 256>>>(Wv, pwvc, Dm, wLo);      // 3
    conv_cols4<<<dim3(Dm / 1024, Dm / 2), 256>>>(Wo, pwoc, Dm, wLo);      // 4

    // QKV projections                                                     5,6,7
    gemm_tc<0><<<gQ, 256, GSMEM_BYTES>>>(pxc, aLoX, pwqc, wLo, bq, pq,
        Tt, Dm, Dm, nullptr, nullptr, nullptr, nullptr);
    gemm_tc<0><<<gQ, 256, GSMEM_BYTES>>>(pxc, aLoX, pwkc, wLo, bk, pk,
        Tt, Dm, Dm, nullptr, nullptr, nullptr, nullptr);
    gemm_tc<0><<<gQ, 256, GSMEM_BYTES>>>(pxc, aLoX, pwvc, wLo, bv, pv,
        Tt, Dm, Dm, nullptr, nullptr, nullptr, nullptr);

    // flash attention (emits split attc planes)
    attn_tc<<<dim3(Sq / 64, Bc * Hh), 128>>>(pq, pk, pv, (uint32_t*)pat);

    // output projection + residual LN1 (emits split x1 planes)
    gemm_tc<0><<<gQ, 256, GSMEM_BYTES>>>((uint32_t*)pat, aLoX, pwoc, wLo, bo, ppr,
        Tt, Dm, Dm, nullptr, nullptr, nullptr, nullptr);
    ln_kernel<<<Tt, 256>>>(x, ppr, g1, beta1, px1, px1c);

    // MoE: routing + sparse expert GEMMs
    zero_kernel<<<2048, 256>>>(pmoe, pcnt, pgs);
    gate_kernel<<<Tt, 128>>>(px1, gateW, gateb, pcnt, ptok, pwt, pgs);
    offsets_kernel<<<1, 32>>>(pcnt, poff);

    conv_cols4<<<dim3(Ff / 1024, Ee * Dm / 2), 256>>>(eW1, pw1c, Ff, w1Lo);
    gemm_tc<1><<<dim3(Ff / 128, Tt / 128, Ee), 256, GSMEM_BYTES>>>(
        px1c, aLoX, pw1c, w1Lo, eb1, ph, Tt, Ff, Dm, pcnt, poff, ptok, pwt);

    conv_cols4<<<dim3(Dm / 1024, Ee * Ff / 2), 256>>>(eW2, pw2c, Dm, w2Lo);
    gemm_tc<2><<<dim3(Dm / 128, Tt / 128, Ee), 256, GSMEM_BYTES>>>(
        (uint32_t*)ph, hLo, pw2c, w2Lo, eb2, pmoe, Tt, Dm, Ff, pcnt, poff, ptok, pwt);

    // final residual LN2 -> output
    ln_kernel<<<Tt, 256>>>(px1, pmoe, g2, beta2, out, nullptr);

    // aux loss scalar appended after the [B,S,D] tensor
    if (out_size > Tt * Dm)
        aux_kernel<<<1, 32>>>(pcnt, pgs, out + (size_t)Tt * Dm);
}